// round 11
// baseline (speedup 1.0000x reference)
#include <cuda_runtime.h>
#include <cuda_fp16.h>
#include <math.h>
#include <stdint.h>

// ============================================================================
// FusedExpertsWrapper — FP16 mma.sync(m16n8k16) + cp.async.bulk, warp-
// autonomous pipeline, fragment-order packed operands (R11).
//   GEMM1: gu = x@w1 + b1 ; act = silu(gu_even)*gu_odd
//   GEMM2: out = act@w2 + b2
// R11 vs R10: 128-thread CTAs, 4 warps of 64x64 (acc=128 regs; 2x128thr -> 256
// regs/thread budget, no spill) -> smem crossbar per chunk-pair 256KB -> 192KB,
// relieving the co-bound crossbar (was ~98% of tensor-busy cycles).
// pack_w2 forked onto a second stream to overlap GEMM1 (graph-capture-legal
// event fork/join). fp32 accumulate; rel_err ~5e-4 (threshold 1e-3).
// ============================================================================

#define E_EXPERTS 8
#define HDIM      2048
#define IDIM      2048
#define F2I       4096
#define ROWS      4096

// ---------------- tiling ----------------
#define BM      128
#define BN      128
#define BK      64
#define STAGES  3
#define A_BYTES    16384                     // 128 x 64 fp16
#define B_BYTES    16384                     // 64 x 128 fp16
#define STG_BYTES  (A_BYTES + B_BYTES)       // 32768
#define DYN_SMEM   (STAGES * STG_BYTES)      // 98304 -> 2 CTAs/SM
#define NCHUNK  (HDIM / BK)                  // 32
#define NWARPS  4
#define A_U4    1024                         // uint4 per A block
#define B_U2    2048                         // uint2 per B block

// ---------------- packed scratch (fragment-order fp16) ----------------
__device__ uint4 g_xp  [(size_t)E_EXPERTS * 32 * NCHUNK * A_U4];
__device__ uint4 g_actp[(size_t)E_EXPERTS * 32 * NCHUNK * A_U4];
__device__ uint2 g_w1p [(size_t)E_EXPERTS * 32 * NCHUNK * B_U2];
__device__ uint2 g_w2p [(size_t)E_EXPERTS * 16 * NCHUNK * B_U2];

__device__ __forceinline__ uint32_t f2h2(float lo, float hi) {
    __half2 h = __floats2half2_rn(lo, hi);
    return *reinterpret_cast<uint32_t*>(&h);
}
__device__ __forceinline__ uint32_t smem_to_u32(const void* p) {
    uint32_t a;
    asm("{ .reg .u64 t; cvta.to.shared.u64 t, %1; cvt.u32.u64 %0, t; }" : "=r"(a) : "l"(p));
    return a;
}

#define MBARRIER_INIT(addr, cnt) \
    asm volatile("mbarrier.init.shared.b64 [%0], %1;" :: "r"((uint32_t)(addr)), "r"((uint32_t)(cnt)) : "memory")
#define MBARRIER_EXPECT_TX(addr, bytes) \
    asm volatile("mbarrier.arrive.expect_tx.shared.b64 _, [%0], %1;" :: "r"((uint32_t)(addr)), "r"((uint32_t)(bytes)) : "memory")
#define MBARRIER_ARRIVE(addr) \
    asm volatile("mbarrier.arrive.shared.b64 _, [%0];" :: "r"((uint32_t)(addr)) : "memory")
#define FENCE_PROXY_ASYNC() asm volatile("fence.proxy.async.shared::cta;" ::: "memory")

#define MBARRIER_WAIT_PARITY(mbar_smem_addr, phase_parity) do { \
    uint32_t _mbar = (uint32_t)(mbar_smem_addr); \
    uint32_t _parity = (uint32_t)(phase_parity); \
    uint32_t _done; \
    asm volatile( \
        "{\n\t.reg .pred p;\n\t" \
        "mbarrier.try_wait.parity.acquire.cta.shared::cta.b64 p, [%1], %2;\n\t" \
        "selp.b32 %0, 1, 0, p;\n\t}" \
        : "=r"(_done) : "r"(_mbar), "r"(_parity) : "memory"); \
    if (!_done) { \
        asm volatile( \
            "{\n\t.reg .pred P1;\n\t" \
            "WAIT_LOOP_%=:\n\t" \
            "mbarrier.try_wait.parity.acquire.cta.shared::cta.b64 P1, [%0], %1, 0x989680;\n\t" \
            "@P1 bra.uni WAIT_DONE_%=;\n\t" \
            "bra.uni WAIT_LOOP_%=;\n\t" \
            "WAIT_DONE_%=:\n\t}" \
            :: "r"(_mbar), "r"(_parity) : "memory"); \
    } \
} while (0)

#define MBARRIER_WAIT_PARITY_RELAXED(mbar_smem_addr, phase_parity) do { \
    uint32_t _mbar = (uint32_t)(mbar_smem_addr); \
    uint32_t _parity = (uint32_t)(phase_parity); \
    uint32_t _done; \
    asm volatile( \
        "{\n\t.reg .pred p;\n\t" \
        "mbarrier.try_wait.parity.relaxed.cta.shared::cta.b64 p, [%1], %2, 0x989680;\n\t" \
        "selp.b32 %0, 1, 0, p;\n\t}" \
        : "=r"(_done) : "r"(_mbar), "r"(_parity) : "memory"); \
    if (!_done) { \
        asm volatile( \
            "{\n\t.reg .pred P1;\n\t" \
            "WAIT_LOOP_%=:\n\t" \
            "mbarrier.try_wait.parity.relaxed.cta.shared::cta.b64 P1, [%0], %1, 0x989680;\n\t" \
            "@P1 bra.uni WAIT_DONE_%=;\n\t" \
            "bra.uni WAIT_LOOP_%=;\n\t" \
            "WAIT_DONE_%=:\n\t}" \
            :: "r"(_mbar), "r"(_parity) : "memory"); \
    } \
} while (0)

__device__ __forceinline__ void bulk_g2s(uint32_t sdst, const void* gsrc,
                                         uint32_t bytes, uint32_t mbar) {
    asm volatile(
        "cp.async.bulk.shared::cluster.global.mbarrier::complete_tx::bytes "
        "[%0], [%1], %2, [%3];"
        :: "r"(sdst), "l"(gsrc), "r"(bytes), "r"(mbar) : "memory");
}

#define MMA_F16(d, av, bv) \
    asm volatile("mma.sync.aligned.m16n8k16.row.col.f32.f16.f16.f32 " \
        "{%0,%1,%2,%3}, {%4,%5,%6,%7}, {%8,%9}, {%0,%1,%2,%3};" \
        : "+f"((d)[0]), "+f"((d)[1]), "+f"((d)[2]), "+f"((d)[3]) \
        : "r"((av).x), "r"((av).y), "r"((av).z), "r"((av).w), \
          "r"((bv).x), "r"((bv).y))

// ============================ main GEMM kernel ============================
// 128 threads = 4 warps as 2(M)x2(N); warp tile 64x64; per-warp 4x8 m16n8k16.
// Fragment layout (PTX m16n8k16.f16, row.col):
//   A uint4 at ((ks*8+mblk)*32+lane): a0=(m=g,k=2q,2q+1) a1=(g+8,..)
//                                     a2=(g,8+2q,..)     a3=(g+8,8+2q,..)
//   B uint2 at ((ks*16+nblk)*32+lane): b0=(k=2q,2q+1; n=g) b1=(k=8+2q,..; n=g)
//   C: c0=(g,2q) c1=(g,2q+1) c2=(g+8,2q) c3=(g+8,2q+1)
template <int MODE>
__global__ void __launch_bounds__(128, 2)
moe_gemm(const uint4* __restrict__ Ap,
         const uint2* __restrict__ Bp,
         const float* __restrict__ bias,
         float* __restrict__ outp)
{
    extern __shared__ __align__(1024) char smem_c[];
    __shared__ __align__(8) unsigned long long mb[2 * STAGES];   // full[0..2], empty[3..5]

    const int NT    = (MODE == 0) ? 32 : 16;
    const int tid   = threadIdx.x;
    const int mtile = blockIdx.x;
    const int ntile = blockIdx.y;
    const int e     = blockIdx.z;

    const int wid  = tid >> 5;                 // 0..3
    const int lane = tid & 31;
    const int g    = lane >> 2;                // 0..7
    const int q    = lane & 3;                 // 0..3
    const int wm   = wid & 1;                  // M half (64 rows)
    const int wn   = wid >> 1;                 // N half (64 cols)

    const uint4* Abase = Ap + (((size_t)e * 32 + mtile) * NCHUNK) * A_U4;
    const uint2* Bbase = Bp + (((size_t)e * NT + ntile) * NCHUNK) * B_U2;

    const uint32_t smem_u = smem_to_u32(smem_c);
    const uint32_t mb_u   = smem_to_u32(mb);
    #define FULL_MB(s)  (mb_u + (s) * 8u)
    #define EMPTY_MB(s) (mb_u + (STAGES + (s)) * 8u)

    if (tid == 0) {
        #pragma unroll
        for (int s = 0; s < STAGES; s++) {
            MBARRIER_INIT(FULL_MB(s), 1);
            MBARRIER_INIT(EMPTY_MB(s), NWARPS);
        }
        FENCE_PROXY_ASYNC();
    }
    __syncthreads();   // mbarrier init visible

    if (tid == 0) {
        #pragma unroll
        for (int p = 0; p < 2; p++) {
            MBARRIER_EXPECT_TX(FULL_MB(p), STG_BYTES);
            bulk_g2s(smem_u + p * STG_BYTES,           Abase + (size_t)p * A_U4, A_BYTES, FULL_MB(p));
            bulk_g2s(smem_u + p * STG_BYTES + A_BYTES, Bbase + (size_t)p * B_U2, B_BYTES, FULL_MB(p));
        }
    }

    float acc[4][8][4];
    #pragma unroll
    for (int mt = 0; mt < 4; mt++)
        #pragma unroll
        for (int nt = 0; nt < 8; nt++)
            #pragma unroll
            for (int r = 0; r < 4; r++) acc[mt][nt][r] = 0.0f;

    int s = 0;
    for (int c = 0; c < NCHUNK; c++) {
        if (tid == 0) {
            const int cn = c + 2;
            if (cn < NCHUNK) {
                const int spp = cn % 3;
                if (c >= 1) {
                    const int k = cn / 3;
                    MBARRIER_WAIT_PARITY_RELAXED(EMPTY_MB(spp), (k + 1) & 1);
                }
                MBARRIER_EXPECT_TX(FULL_MB(spp), STG_BYTES);
                bulk_g2s(smem_u + spp * STG_BYTES,           Abase + (size_t)cn * A_U4, A_BYTES, FULL_MB(spp));
                bulk_g2s(smem_u + spp * STG_BYTES + A_BYTES, Bbase + (size_t)cn * B_U2, B_BYTES, FULL_MB(spp));
            }
        }

        MBARRIER_WAIT_PARITY(FULL_MB(s), (c / 3) & 1);

        const uint4* fA = reinterpret_cast<const uint4*>(smem_c + s * STG_BYTES)
                        + wm * 128 + lane;                 // + ks*256 + mt*32
        const uint2* fB = reinterpret_cast<const uint2*>(smem_c + s * STG_BYTES + A_BYTES)
                        + wn * 256 + lane;                 // + ks*512 + nt*32

        #pragma unroll
        for (int ks = 0; ks < 4; ks++) {
            uint4 a4[4];
            #pragma unroll
            for (int mt = 0; mt < 4; mt++) a4[mt] = fA[ks * 256 + mt * 32];
            uint2 b2[8];
            #pragma unroll
            for (int nt = 0; nt < 8; nt++) b2[nt] = fB[ks * 512 + nt * 32];
            #pragma unroll
            for (int mt = 0; mt < 4; mt++)
                #pragma unroll
                for (int nt = 0; nt < 8; nt++)
                    MMA_F16(acc[mt][nt], a4[mt], b2[nt]);
        }

        __syncwarp();
        if (lane == 0) MBARRIER_ARRIVE(EMPTY_MB(s));

        s = (s == STAGES - 1) ? 0 : s + 1;
    }

    if (MODE == 0) {
        // ---- epilogue: bias + silu*up -> stage f32 act tile in smem,
        //      then repack to fp16 fragment order (GEMM2 A-block (mtile, ntile)).
        __syncthreads();                       // all warps done with pipeline smem
        float* act_s = reinterpret_cast<float*>(smem_c);   // [128][65]
        #pragma unroll
        for (int nt = 0; nt < 8; nt++) {
            const int f0 = ntile * BN + wn * 64 + nt * 8 + 2 * q;   // gate col (even)
            const float2 bgu = *reinterpret_cast<const float2*>(
                bias + (size_t)e * F2I + f0);
            const int ic = wn * 32 + nt * 4 + q;                    // local icol 0..63
            #pragma unroll
            for (int mt = 0; mt < 4; mt++) {
                const int r0 = wm * 64 + mt * 16 + g;
                float gg0 = acc[mt][nt][0] + bgu.x;
                float uu0 = acc[mt][nt][1] + bgu.y;
                float gg1 = acc[mt][nt][2] + bgu.x;
                float uu1 = acc[mt][nt][3] + bgu.y;
                act_s[r0 * 65 + ic]       = (gg0 * uu0) / (1.0f + __expf(-gg0));
                act_s[(r0 + 8) * 65 + ic] = (gg1 * uu1) / (1.0f + __expf(-gg1));
            }
        }
        __syncthreads();
        uint4* dst = g_actp + (((size_t)e * 32 + mtile) * NCHUNK + ntile) * A_U4;
        #pragma unroll
        for (int r = 0; r < 8; r++) {
            const int j    = tid + r * 128;            // 0..1023
            const int ln   = j & 31;
            const int mblk = (j >> 5) & 7;
            const int ks   = j >> 8;
            const int gg   = ln >> 2, qq = ln & 3;
            const int m0 = mblk * 16 + gg;
            const int k0 = ks * 16 + 2 * qq;
            uint4 o;
            o.x = f2h2(act_s[m0 * 65 + k0],           act_s[m0 * 65 + k0 + 1]);
            o.y = f2h2(act_s[(m0 + 8) * 65 + k0],     act_s[(m0 + 8) * 65 + k0 + 1]);
            o.z = f2h2(act_s[m0 * 65 + k0 + 8],       act_s[m0 * 65 + k0 + 9]);
            o.w = f2h2(act_s[(m0 + 8) * 65 + k0 + 8], act_s[(m0 + 8) * 65 + k0 + 9]);
            dst[j] = o;
        }
    } else {
        #pragma unroll
        for (int nt = 0; nt < 8; nt++) {
            const int h = ntile * BN + wn * 64 + nt * 8 + 2 * q;
            const float2 bb = *reinterpret_cast<const float2*>(
                bias + (size_t)e * HDIM + h);
            #pragma unroll
            for (int mt = 0; mt < 4; mt++) {
                const int m = mtile * BM + wm * 64 + mt * 16 + g;
                float* o0 = outp + ((size_t)e * ROWS + m) * HDIM + h;
                *reinterpret_cast<float2*>(o0) =
                    make_float2(acc[mt][nt][0] + bb.x, acc[mt][nt][1] + bb.y);
                *reinterpret_cast<float2*>(o0 + 8 * (size_t)HDIM) =
                    make_float2(acc[mt][nt][2] + bb.x, acc[mt][nt][3] + bb.y);
            }
        }
    }
}

// ============================ prep kernels ============================

// x [b][e][m][h] -> g_xp fragment-order fp16; one uint4 per thread.
__global__ void pack_x(const float* __restrict__ in) {
    const uint32_t i = blockIdx.x * 256 + threadIdx.x;   // 2^23 total
    const int ln    = i & 31;
    const int mblk  = (i >> 5) & 7;
    const int ks    = (i >> 8) & 3;
    const int c     = (i >> 10) & 31;
    const int mtile = (i >> 15) & 31;
    const int e     = i >> 20;
    const int g = ln >> 2, q = ln & 3;
    const int m0 = mtile * 128 + mblk * 16 + g;          // m0 and m0+8 share b
    const int k0 = c * 64 + ks * 16 + 2 * q;
    const int b = m0 >> 9, mm = m0 & 511;
    const float* row0 = in + (((size_t)(b * E_EXPERTS + e) << 9) + mm) * HDIM + k0;
    const float* row1 = row0 + 8 * (size_t)HDIM;
    uint4 o;
    o.x = f2h2(row0[0], row0[1]);
    o.y = f2h2(row1[0], row1[1]);
    o.z = f2h2(row0[8], row0[9]);
    o.w = f2h2(row1[8], row1[9]);
    g_xp[i] = o;
}

// weights [e][2048][NB] -> fragment-order fp16 B; one uint2 per thread.
__global__ void pack_w(const float* __restrict__ in, uint2* __restrict__ outp,
                       int NT, int NB) {
    const uint32_t i = blockIdx.x * 256 + threadIdx.x;
    const int ln   = i & 31;
    const int nblk = (i >> 5) & 15;
    const int ks   = (i >> 9) & 3;
    const int c    = (i >> 11) & 31;
    const uint32_t r = i >> 16;
    const int ntile = (int)(r % (uint32_t)NT);
    const int e     = (int)(r / (uint32_t)NT);
    const int g = ln >> 2, q = ln & 3;
    const int n0 = ntile * 128 + nblk * 8 + g;
    const int k0 = c * 64 + ks * 16 + 2 * q;
    const float* src = in + ((size_t)e * 2048 + k0) * NB + n0;
    uint2 o;
    o.x = f2h2(src[0],             src[(size_t)NB]);        // k0, k0+1
    o.y = f2h2(src[(size_t)8 * NB], src[(size_t)9 * NB]);   // k0+8, k0+9
    outp[i] = o;
}

// ============================ host side ============================

extern "C" void kernel_launch(void* const* d_in, const int* in_sizes, int n_in,
                              void* d_out, int out_size)
{
    const float* dispatched = (const float*)d_in[0];   // (1,8,8,512,2048)
    const float* w1         = (const float*)d_in[1];   // (8,2048,4096)
    const float* w1_bias    = (const float*)d_in[2];   // (8,4096)
    const float* w2         = (const float*)d_in[3];   // (8,2048,2048)
    const float* w2_bias    = (const float*)d_in[4];   // (8,2048)
    float* out = (float*)d_out;                        // (8,1,4096,2048) fp32
    (void)in_sizes; (void)n_in; (void)out_size;

    static uint4 *p_xp = nullptr, *p_actp = nullptr;
    static uint2 *p_w1p = nullptr, *p_w2p = nullptr;
    static cudaStream_t s2 = nullptr;
    static cudaEvent_t ev_fork = nullptr, ev_join = nullptr;
    static bool init_done = false;
    if (!init_done) {
        cudaGetSymbolAddress((void**)&p_xp,   g_xp);
        cudaGetSymbolAddress((void**)&p_actp, g_actp);
        cudaGetSymbolAddress((void**)&p_w1p,  g_w1p);
        cudaGetSymbolAddress((void**)&p_w2p,  g_w2p);
        cudaFuncSetAttribute(moe_gemm<0>, cudaFuncAttributeMaxDynamicSharedMemorySize, DYN_SMEM);
        cudaFuncSetAttribute(moe_gemm<1>, cudaFuncAttributeMaxDynamicSharedMemorySize, DYN_SMEM);
        cudaStreamCreateWithFlags(&s2, cudaStreamNonBlocking);
        cudaEventCreateWithFlags(&ev_fork, cudaEventDisableTiming);
        cudaEventCreateWithFlags(&ev_join, cudaEventDisableTiming);
        init_done = true;
    }

    // fork: pack_w2 runs on s2, overlapping pack_x/pack_w1/GEMM1 on stream 0
    cudaEventRecord(ev_fork, 0);
    cudaStreamWaitEvent(s2, ev_fork, 0);
    pack_w<<<32768, 256, 0, s2>>>(w2, p_w2p, 16, HDIM);
    cudaEventRecord(ev_join, s2);

    pack_x<<<32768, 256>>>(dispatched);
    pack_w<<<65536, 256>>>(w1, p_w1p, 32, F2I);

    // GEMM1: grid (32 mtiles, 32 ntiles, 8 experts), 128 threads
    moe_gemm<0><<<dim3(32, 32, E_EXPERTS), 128, DYN_SMEM>>>(p_xp, p_w1p, w1_bias, nullptr);

    // join: GEMM2 needs g_w2p
    cudaStreamWaitEvent(0, ev_join, 0);
    // GEMM2: grid (32, 16, 8)
    moe_gemm<1><<<dim3(32, 16, E_EXPERTS), 128, DYN_SMEM>>>(p_actp, p_w2p, w2_bias, out);
}

// round 12
// speedup vs baseline: 1.0299x; 1.0299x over previous
#include <cuda_runtime.h>
#include <cuda_fp16.h>
#include <math.h>
#include <stdint.h>

// ============================================================================
// FusedExpertsWrapper — FP16 mma.sync(m16n8k16) + cp.async.bulk, warp-
// autonomous pipeline, fragment-order packed operands (R12 = R10 geometry +
// stream-forked pack_w2).
//   GEMM1: gu = x@w1 + b1 ; act = silu(gu_even)*gu_odd
//   GEMM2: out = act@w2 + b2
// R10 geometry restored (256 thr, 8 warps 64x32, 2 CTAs/SM = 4 warps/SMSP —
// R8/R11 both showed 2 warps/SMSP cannot hide boundary latency). pack_w2 forked
// onto a second stream: it only feeds GEMM2 and is DRAM-bound, so it hides
// fully under tensor-bound GEMM1. fp32 accumulate; rel_err ~5e-4.
// ============================================================================

#define E_EXPERTS 8
#define HDIM      2048
#define IDIM      2048
#define F2I       4096
#define ROWS      4096

// ---------------- tiling ----------------
#define BM      128
#define BN      128
#define BK      64
#define STAGES  3
#define A_BYTES    16384                     // 128 x 64 fp16
#define B_BYTES    16384                     // 64 x 128 fp16
#define STG_BYTES  (A_BYTES + B_BYTES)       // 32768
#define DYN_SMEM   (STAGES * STG_BYTES)      // 98304 -> 2 CTAs/SM
#define NCHUNK  (HDIM / BK)                  // 32
#define NWARPS  8
#define A_U4    1024                         // uint4 per A block
#define B_U2    2048                         // uint2 per B block

// ---------------- packed scratch (fragment-order fp16) ----------------
// A blocks: [e][mtile 32][chunk 32][1024 uint4]
__device__ uint4 g_xp  [(size_t)E_EXPERTS * 32 * NCHUNK * A_U4];
__device__ uint4 g_actp[(size_t)E_EXPERTS * 32 * NCHUNK * A_U4];
// B blocks: [e][ntile NT][chunk 32][2048 uint2]
__device__ uint2 g_w1p [(size_t)E_EXPERTS * 32 * NCHUNK * B_U2];
__device__ uint2 g_w2p [(size_t)E_EXPERTS * 16 * NCHUNK * B_U2];

__device__ __forceinline__ uint32_t f2h2(float lo, float hi) {
    __half2 h = __floats2half2_rn(lo, hi);
    return *reinterpret_cast<uint32_t*>(&h);
}
__device__ __forceinline__ uint32_t smem_to_u32(const void* p) {
    uint32_t a;
    asm("{ .reg .u64 t; cvta.to.shared.u64 t, %1; cvt.u32.u64 %0, t; }" : "=r"(a) : "l"(p));
    return a;
}

#define MBARRIER_INIT(addr, cnt) \
    asm volatile("mbarrier.init.shared.b64 [%0], %1;" :: "r"((uint32_t)(addr)), "r"((uint32_t)(cnt)) : "memory")
#define MBARRIER_EXPECT_TX(addr, bytes) \
    asm volatile("mbarrier.arrive.expect_tx.shared.b64 _, [%0], %1;" :: "r"((uint32_t)(addr)), "r"((uint32_t)(bytes)) : "memory")
#define MBARRIER_ARRIVE(addr) \
    asm volatile("mbarrier.arrive.shared.b64 _, [%0];" :: "r"((uint32_t)(addr)) : "memory")
#define FENCE_PROXY_ASYNC() asm volatile("fence.proxy.async.shared::cta;" ::: "memory")

#define MBARRIER_WAIT_PARITY(mbar_smem_addr, phase_parity) do { \
    uint32_t _mbar = (uint32_t)(mbar_smem_addr); \
    uint32_t _parity = (uint32_t)(phase_parity); \
    uint32_t _done; \
    asm volatile( \
        "{\n\t.reg .pred p;\n\t" \
        "mbarrier.try_wait.parity.acquire.cta.shared::cta.b64 p, [%1], %2;\n\t" \
        "selp.b32 %0, 1, 0, p;\n\t}" \
        : "=r"(_done) : "r"(_mbar), "r"(_parity) : "memory"); \
    if (!_done) { \
        asm volatile( \
            "{\n\t.reg .pred P1;\n\t" \
            "WAIT_LOOP_%=:\n\t" \
            "mbarrier.try_wait.parity.acquire.cta.shared::cta.b64 P1, [%0], %1, 0x989680;\n\t" \
            "@P1 bra.uni WAIT_DONE_%=;\n\t" \
            "bra.uni WAIT_LOOP_%=;\n\t" \
            "WAIT_DONE_%=:\n\t}" \
            :: "r"(_mbar), "r"(_parity) : "memory"); \
    } \
} while (0)

#define MBARRIER_WAIT_PARITY_RELAXED(mbar_smem_addr, phase_parity) do { \
    uint32_t _mbar = (uint32_t)(mbar_smem_addr); \
    uint32_t _parity = (uint32_t)(phase_parity); \
    uint32_t _done; \
    asm volatile( \
        "{\n\t.reg .pred p;\n\t" \
        "mbarrier.try_wait.parity.relaxed.cta.shared::cta.b64 p, [%1], %2, 0x989680;\n\t" \
        "selp.b32 %0, 1, 0, p;\n\t}" \
        : "=r"(_done) : "r"(_mbar), "r"(_parity) : "memory"); \
    if (!_done) { \
        asm volatile( \
            "{\n\t.reg .pred P1;\n\t" \
            "WAIT_LOOP_%=:\n\t" \
            "mbarrier.try_wait.parity.relaxed.cta.shared::cta.b64 P1, [%0], %1, 0x989680;\n\t" \
            "@P1 bra.uni WAIT_DONE_%=;\n\t" \
            "bra.uni WAIT_LOOP_%=;\n\t" \
            "WAIT_DONE_%=:\n\t}" \
            :: "r"(_mbar), "r"(_parity) : "memory"); \
    } \
} while (0)

__device__ __forceinline__ void bulk_g2s(uint32_t sdst, const void* gsrc,
                                         uint32_t bytes, uint32_t mbar) {
    asm volatile(
        "cp.async.bulk.shared::cluster.global.mbarrier::complete_tx::bytes "
        "[%0], [%1], %2, [%3];"
        :: "r"(sdst), "l"(gsrc), "r"(bytes), "r"(mbar) : "memory");
}

#define MMA_F16(d, av, bv) \
    asm volatile("mma.sync.aligned.m16n8k16.row.col.f32.f16.f16.f32 " \
        "{%0,%1,%2,%3}, {%4,%5,%6,%7}, {%8,%9}, {%0,%1,%2,%3};" \
        : "+f"((d)[0]), "+f"((d)[1]), "+f"((d)[2]), "+f"((d)[3]) \
        : "r"((av).x), "r"((av).y), "r"((av).z), "r"((av).w), \
          "r"((bv).x), "r"((bv).y))

// ============================ main GEMM kernel ============================
// 256 threads = 8 warps as 2(M)x4(N); warp tile 64x32; per-warp 4x4 m16n8k16.
// Fragment layout (PTX m16n8k16.f16, row.col):
//   A uint4 at ((ks*8+mblk)*32+lane): a0=(m=g,k=2q,2q+1) a1=(g+8,..)
//                                     a2=(g,8+2q,..)     a3=(g+8,8+2q,..)
//   B uint2 at ((ks*16+nblk)*32+lane): b0=(k=2q,2q+1; n=g) b1=(k=8+2q,..; n=g)
//   C: c0=(g,2q) c1=(g,2q+1) c2=(g+8,2q) c3=(g+8,2q+1)
template <int MODE>
__global__ void __launch_bounds__(256, 2)
moe_gemm(const uint4* __restrict__ Ap,
         const uint2* __restrict__ Bp,
         const float* __restrict__ bias,
         float* __restrict__ outp)
{
    extern __shared__ __align__(1024) char smem_c[];
    __shared__ __align__(8) unsigned long long mb[2 * STAGES];   // full[0..2], empty[3..5]

    const int NT    = (MODE == 0) ? 32 : 16;
    const int tid   = threadIdx.x;
    const int mtile = blockIdx.x;
    const int ntile = blockIdx.y;
    const int e     = blockIdx.z;

    const int wid  = tid >> 5;                 // 0..7
    const int lane = tid & 31;
    const int g    = lane >> 2;                // 0..7
    const int q    = lane & 3;                 // 0..3
    const int wm   = wid & 1;                  // M half
    const int wn   = wid >> 1;                 // N quarter 0..3

    const uint4* Abase = Ap + (((size_t)e * 32 + mtile) * NCHUNK) * A_U4;
    const uint2* Bbase = Bp + (((size_t)e * NT + ntile) * NCHUNK) * B_U2;

    const uint32_t smem_u = smem_to_u32(smem_c);
    const uint32_t mb_u   = smem_to_u32(mb);
    #define FULL_MB(s)  (mb_u + (s) * 8u)
    #define EMPTY_MB(s) (mb_u + (STAGES + (s)) * 8u)

    if (tid == 0) {
        #pragma unroll
        for (int s = 0; s < STAGES; s++) {
            MBARRIER_INIT(FULL_MB(s), 1);
            MBARRIER_INIT(EMPTY_MB(s), NWARPS);
        }
        FENCE_PROXY_ASYNC();
    }
    __syncthreads();   // mbarrier init visible

    if (tid == 0) {
        #pragma unroll
        for (int p = 0; p < 2; p++) {
            MBARRIER_EXPECT_TX(FULL_MB(p), STG_BYTES);
            bulk_g2s(smem_u + p * STG_BYTES,           Abase + (size_t)p * A_U4, A_BYTES, FULL_MB(p));
            bulk_g2s(smem_u + p * STG_BYTES + A_BYTES, Bbase + (size_t)p * B_U2, B_BYTES, FULL_MB(p));
        }
    }

    float acc[4][4][4];
    #pragma unroll
    for (int mt = 0; mt < 4; mt++)
        #pragma unroll
        for (int nt = 0; nt < 4; nt++)
            #pragma unroll
            for (int r = 0; r < 4; r++) acc[mt][nt][r] = 0.0f;

    int s = 0;
    for (int c = 0; c < NCHUNK; c++) {
        if (tid == 0) {
            const int cn = c + 2;
            if (cn < NCHUNK) {
                const int spp = cn % 3;
                if (c >= 1) {
                    const int k = cn / 3;
                    MBARRIER_WAIT_PARITY_RELAXED(EMPTY_MB(spp), (k + 1) & 1);
                }
                MBARRIER_EXPECT_TX(FULL_MB(spp), STG_BYTES);
                bulk_g2s(smem_u + spp * STG_BYTES,           Abase + (size_t)cn * A_U4, A_BYTES, FULL_MB(spp));
                bulk_g2s(smem_u + spp * STG_BYTES + A_BYTES, Bbase + (size_t)cn * B_U2, B_BYTES, FULL_MB(spp));
            }
        }

        MBARRIER_WAIT_PARITY(FULL_MB(s), (c / 3) & 1);

        const uint4* fA = reinterpret_cast<const uint4*>(smem_c + s * STG_BYTES)
                        + wm * 128 + lane;                 // + ks*256 + mt*32
        const uint2* fB = reinterpret_cast<const uint2*>(smem_c + s * STG_BYTES + A_BYTES)
                        + wn * 128 + lane;                 // + ks*512 + nt*32

        #pragma unroll
        for (int ks = 0; ks < 4; ks++) {
            uint4 a4[4];
            #pragma unroll
            for (int mt = 0; mt < 4; mt++) a4[mt] = fA[ks * 256 + mt * 32];
            uint2 b2[4];
            #pragma unroll
            for (int nt = 0; nt < 4; nt++) b2[nt] = fB[ks * 512 + nt * 32];
            #pragma unroll
            for (int mt = 0; mt < 4; mt++)
                #pragma unroll
                for (int nt = 0; nt < 4; nt++)
                    MMA_F16(acc[mt][nt], a4[mt], b2[nt]);
        }

        __syncwarp();
        if (lane == 0) MBARRIER_ARRIVE(EMPTY_MB(s));

        s = (s == STAGES - 1) ? 0 : s + 1;
    }

    if (MODE == 0) {
        // ---- epilogue: bias + silu*up -> stage f32 act tile in smem,
        //      then repack to fp16 fragment order (GEMM2 A-block (mtile, ntile)).
        __syncthreads();                       // all warps done with pipeline smem
        float* act_s = reinterpret_cast<float*>(smem_c);   // [128][65]
        #pragma unroll
        for (int nt = 0; nt < 4; nt++) {
            const int f0 = ntile * BN + wn * 32 + nt * 8 + 2 * q;   // gate col (even)
            const float2 bgu = *reinterpret_cast<const float2*>(
                bias + (size_t)e * F2I + f0);
            const int ic = wn * 16 + nt * 4 + q;                    // local icol 0..63
            #pragma unroll
            for (int mt = 0; mt < 4; mt++) {
                const int r0 = wm * 64 + mt * 16 + g;
                float gg0 = acc[mt][nt][0] + bgu.x;
                float uu0 = acc[mt][nt][1] + bgu.y;
                float gg1 = acc[mt][nt][2] + bgu.x;
                float uu1 = acc[mt][nt][3] + bgu.y;
                act_s[r0 * 65 + ic]       = (gg0 * uu0) / (1.0f + __expf(-gg0));
                act_s[(r0 + 8) * 65 + ic] = (gg1 * uu1) / (1.0f + __expf(-gg1));
            }
        }
        __syncthreads();
        uint4* dst = g_actp + (((size_t)e * 32 + mtile) * NCHUNK + ntile) * A_U4;
        #pragma unroll
        for (int r = 0; r < 4; r++) {
            const int j    = tid + r * 256;            // 0..1023
            const int ln   = j & 31;
            const int mblk = (j >> 5) & 7;
            const int ks   = j >> 8;
            const int gg   = ln >> 2, qq = ln & 3;
            const int m0 = mblk * 16 + gg;
            const int k0 = ks * 16 + 2 * qq;
            uint4 o;
            o.x = f2h2(act_s[m0 * 65 + k0],           act_s[m0 * 65 + k0 + 1]);
            o.y = f2h2(act_s[(m0 + 8) * 65 + k0],     act_s[(m0 + 8) * 65 + k0 + 1]);
            o.z = f2h2(act_s[m0 * 65 + k0 + 8],       act_s[m0 * 65 + k0 + 9]);
            o.w = f2h2(act_s[(m0 + 8) * 65 + k0 + 8], act_s[(m0 + 8) * 65 + k0 + 9]);
            dst[j] = o;
        }
    } else {
        #pragma unroll
        for (int nt = 0; nt < 4; nt++) {
            const int h = ntile * BN + wn * 32 + nt * 8 + 2 * q;
            const float2 bb = *reinterpret_cast<const float2*>(
                bias + (size_t)e * HDIM + h);
            #pragma unroll
            for (int mt = 0; mt < 4; mt++) {
                const int m = mtile * BM + wm * 64 + mt * 16 + g;
                float* o0 = outp + ((size_t)e * ROWS + m) * HDIM + h;
                *reinterpret_cast<float2*>(o0) =
                    make_float2(acc[mt][nt][0] + bb.x, acc[mt][nt][1] + bb.y);
                *reinterpret_cast<float2*>(o0 + 8 * (size_t)HDIM) =
                    make_float2(acc[mt][nt][2] + bb.x, acc[mt][nt][3] + bb.y);
            }
        }
    }
}

// ============================ prep kernels ============================

// x [b][e][m][h] -> g_xp fragment-order fp16; one uint4 per thread.
__global__ void pack_x(const float* __restrict__ in) {
    const uint32_t i = blockIdx.x * 256 + threadIdx.x;   // 2^23 total
    const int ln    = i & 31;
    const int mblk  = (i >> 5) & 7;
    const int ks    = (i >> 8) & 3;
    const int c     = (i >> 10) & 31;
    const int mtile = (i >> 15) & 31;
    const int e     = i >> 20;
    const int g = ln >> 2, q = ln & 3;
    const int m0 = mtile * 128 + mblk * 16 + g;          // m0 and m0+8 share b
    const int k0 = c * 64 + ks * 16 + 2 * q;
    const int b = m0 >> 9, mm = m0 & 511;
    const float* row0 = in + (((size_t)(b * E_EXPERTS + e) << 9) + mm) * HDIM + k0;
    const float* row1 = row0 + 8 * (size_t)HDIM;
    uint4 o;
    o.x = f2h2(row0[0], row0[1]);
    o.y = f2h2(row1[0], row1[1]);
    o.z = f2h2(row0[8], row0[9]);
    o.w = f2h2(row1[8], row1[9]);
    g_xp[i] = o;
}

// weights [e][2048][NB] -> fragment-order fp16 B; one uint2 per thread.
__global__ void pack_w(const float* __restrict__ in, uint2* __restrict__ outp,
                       int NT, int NB) {
    const uint32_t i = blockIdx.x * 256 + threadIdx.x;
    const int ln   = i & 31;
    const int nblk = (i >> 5) & 15;
    const int ks   = (i >> 9) & 3;
    const int c    = (i >> 11) & 31;
    const uint32_t r = i >> 16;
    const int ntile = (int)(r % (uint32_t)NT);
    const int e     = (int)(r / (uint32_t)NT);
    const int g = ln >> 2, q = ln & 3;
    const int n0 = ntile * 128 + nblk * 8 + g;
    const int k0 = c * 64 + ks * 16 + 2 * q;
    const float* src = in + ((size_t)e * 2048 + k0) * NB + n0;
    uint2 o;
    o.x = f2h2(src[0],             src[(size_t)NB]);        // k0, k0+1
    o.y = f2h2(src[(size_t)8 * NB], src[(size_t)9 * NB]);   // k0+8, k0+9
    outp[i] = o;
}

// ============================ host side ============================

extern "C" void kernel_launch(void* const* d_in, const int* in_sizes, int n_in,
                              void* d_out, int out_size)
{
    const float* dispatched = (const float*)d_in[0];   // (1,8,8,512,2048)
    const float* w1         = (const float*)d_in[1];   // (8,2048,4096)
    const float* w1_bias    = (const float*)d_in[2];   // (8,4096)
    const float* w2         = (const float*)d_in[3];   // (8,2048,2048)
    const float* w2_bias    = (const float*)d_in[4];   // (8,2048)
    float* out = (float*)d_out;                        // (8,1,4096,2048) fp32
    (void)in_sizes; (void)n_in; (void)out_size;

    static uint4 *p_xp = nullptr, *p_actp = nullptr;
    static uint2 *p_w1p = nullptr, *p_w2p = nullptr;
    static cudaStream_t s2 = nullptr;
    static cudaEvent_t ev_fork = nullptr, ev_join = nullptr;
    static bool init_done = false;
    if (!init_done) {
        cudaGetSymbolAddress((void**)&p_xp,   g_xp);
        cudaGetSymbolAddress((void**)&p_actp, g_actp);
        cudaGetSymbolAddress((void**)&p_w1p,  g_w1p);
        cudaGetSymbolAddress((void**)&p_w2p,  g_w2p);
        cudaFuncSetAttribute(moe_gemm<0>, cudaFuncAttributeMaxDynamicSharedMemorySize, DYN_SMEM);
        cudaFuncSetAttribute(moe_gemm<1>, cudaFuncAttributeMaxDynamicSharedMemorySize, DYN_SMEM);
        cudaStreamCreateWithFlags(&s2, cudaStreamNonBlocking);
        cudaEventCreateWithFlags(&ev_fork, cudaEventDisableTiming);
        cudaEventCreateWithFlags(&ev_join, cudaEventDisableTiming);
        init_done = true;
    }

    // fork: pack_w2 on s2 overlaps pack_x/pack_w1/GEMM1 on stream 0
    cudaEventRecord(ev_fork, 0);
    cudaStreamWaitEvent(s2, ev_fork, 0);
    pack_w<<<32768, 256, 0, s2>>>(w2, p_w2p, 16, HDIM);
    cudaEventRecord(ev_join, s2);

    pack_x<<<32768, 256>>>(dispatched);
    pack_w<<<65536, 256>>>(w1, p_w1p, 32, F2I);

    // GEMM1: grid (32 mtiles, 32 ntiles, 8 experts), 256 threads
    moe_gemm<0><<<dim3(32, 32, E_EXPERTS), 256, DYN_SMEM>>>(p_xp, p_w1p, w1_bias, nullptr);

    // join: GEMM2 needs g_w2p
    cudaStreamWaitEvent(0, ev_join, 0);
    // GEMM2: grid (32, 16, 8)
    moe_gemm<1><<<dim3(32, 16, E_EXPERTS), 256, DYN_SMEM>>>(p_actp, p_w2p, w2_bias, out);
}

// round 13
// speedup vs baseline: 1.0307x; 1.0007x over previous
#include <cuda_runtime.h>
#include <cuda_fp16.h>
#include <math.h>
#include <stdint.h>

// ============================================================================
// FusedExpertsWrapper — FP16 mma.sync(m16n8k16) + cp.async.bulk, warp-
// autonomous pipeline, fragment-order packed operands (R13 = R12 with the
// pack_w2 fork moved AFTER pack_w1 so it overlaps tensor-bound GEMM1 instead
// of contending with the DRAM-bound prep kernels).
//   GEMM1: gu = x@w1 + b1 ; act = silu(gu_even)*gu_odd
//   GEMM2: out = act@w2 + b2
// 256 thr, 8 warps 64x32, BK=64, 3 stages x 32KB, 2 CTAs/SM (4 warps/SMSP —
// R8/R11 showed 2 warps/SMSP cannot hide boundary latency).
// fp32 accumulate; rel_err ~5e-4 (threshold 1e-3).
// ============================================================================

#define E_EXPERTS 8
#define HDIM      2048
#define IDIM      2048
#define F2I       4096
#define ROWS      4096

// ---------------- tiling ----------------
#define BM      128
#define BN      128
#define BK      64
#define STAGES  3
#define A_BYTES    16384                     // 128 x 64 fp16
#define B_BYTES    16384                     // 64 x 128 fp16
#define STG_BYTES  (A_BYTES + B_BYTES)       // 32768
#define DYN_SMEM   (STAGES * STG_BYTES)      // 98304 -> 2 CTAs/SM
#define NCHUNK  (HDIM / BK)                  // 32
#define NWARPS  8
#define A_U4    1024                         // uint4 per A block
#define B_U2    2048                         // uint2 per B block

// ---------------- packed scratch (fragment-order fp16) ----------------
// A blocks: [e][mtile 32][chunk 32][1024 uint4]
__device__ uint4 g_xp  [(size_t)E_EXPERTS * 32 * NCHUNK * A_U4];
__device__ uint4 g_actp[(size_t)E_EXPERTS * 32 * NCHUNK * A_U4];
// B blocks: [e][ntile NT][chunk 32][2048 uint2]
__device__ uint2 g_w1p [(size_t)E_EXPERTS * 32 * NCHUNK * B_U2];
__device__ uint2 g_w2p [(size_t)E_EXPERTS * 16 * NCHUNK * B_U2];

__device__ __forceinline__ uint32_t f2h2(float lo, float hi) {
    __half2 h = __floats2half2_rn(lo, hi);
    return *reinterpret_cast<uint32_t*>(&h);
}
__device__ __forceinline__ uint32_t smem_to_u32(const void* p) {
    uint32_t a;
    asm("{ .reg .u64 t; cvta.to.shared.u64 t, %1; cvt.u32.u64 %0, t; }" : "=r"(a) : "l"(p));
    return a;
}

#define MBARRIER_INIT(addr, cnt) \
    asm volatile("mbarrier.init.shared.b64 [%0], %1;" :: "r"((uint32_t)(addr)), "r"((uint32_t)(cnt)) : "memory")
#define MBARRIER_EXPECT_TX(addr, bytes) \
    asm volatile("mbarrier.arrive.expect_tx.shared.b64 _, [%0], %1;" :: "r"((uint32_t)(addr)), "r"((uint32_t)(bytes)) : "memory")
#define MBARRIER_ARRIVE(addr) \
    asm volatile("mbarrier.arrive.shared.b64 _, [%0];" :: "r"((uint32_t)(addr)) : "memory")
#define FENCE_PROXY_ASYNC() asm volatile("fence.proxy.async.shared::cta;" ::: "memory")

#define MBARRIER_WAIT_PARITY(mbar_smem_addr, phase_parity) do { \
    uint32_t _mbar = (uint32_t)(mbar_smem_addr); \
    uint32_t _parity = (uint32_t)(phase_parity); \
    uint32_t _done; \
    asm volatile( \
        "{\n\t.reg .pred p;\n\t" \
        "mbarrier.try_wait.parity.acquire.cta.shared::cta.b64 p, [%1], %2;\n\t" \
        "selp.b32 %0, 1, 0, p;\n\t}" \
        : "=r"(_done) : "r"(_mbar), "r"(_parity) : "memory"); \
    if (!_done) { \
        asm volatile( \
            "{\n\t.reg .pred P1;\n\t" \
            "WAIT_LOOP_%=:\n\t" \
            "mbarrier.try_wait.parity.acquire.cta.shared::cta.b64 P1, [%0], %1, 0x989680;\n\t" \
            "@P1 bra.uni WAIT_DONE_%=;\n\t" \
            "bra.uni WAIT_LOOP_%=;\n\t" \
            "WAIT_DONE_%=:\n\t}" \
            :: "r"(_mbar), "r"(_parity) : "memory"); \
    } \
} while (0)

#define MBARRIER_WAIT_PARITY_RELAXED(mbar_smem_addr, phase_parity) do { \
    uint32_t _mbar = (uint32_t)(mbar_smem_addr); \
    uint32_t _parity = (uint32_t)(phase_parity); \
    uint32_t _done; \
    asm volatile( \
        "{\n\t.reg .pred p;\n\t" \
        "mbarrier.try_wait.parity.relaxed.cta.shared::cta.b64 p, [%1], %2, 0x989680;\n\t" \
        "selp.b32 %0, 1, 0, p;\n\t}" \
        : "=r"(_done) : "r"(_mbar), "r"(_parity) : "memory"); \
    if (!_done) { \
        asm volatile( \
            "{\n\t.reg .pred P1;\n\t" \
            "WAIT_LOOP_%=:\n\t" \
            "mbarrier.try_wait.parity.relaxed.cta.shared::cta.b64 P1, [%0], %1, 0x989680;\n\t" \
            "@P1 bra.uni WAIT_DONE_%=;\n\t" \
            "bra.uni WAIT_LOOP_%=;\n\t" \
            "WAIT_DONE_%=:\n\t}" \
            :: "r"(_mbar), "r"(_parity) : "memory"); \
    } \
} while (0)

__device__ __forceinline__ void bulk_g2s(uint32_t sdst, const void* gsrc,
                                         uint32_t bytes, uint32_t mbar) {
    asm volatile(
        "cp.async.bulk.shared::cluster.global.mbarrier::complete_tx::bytes "
        "[%0], [%1], %2, [%3];"
        :: "r"(sdst), "l"(gsrc), "r"(bytes), "r"(mbar) : "memory");
}

#define MMA_F16(d, av, bv) \
    asm volatile("mma.sync.aligned.m16n8k16.row.col.f32.f16.f16.f32 " \
        "{%0,%1,%2,%3}, {%4,%5,%6,%7}, {%8,%9}, {%0,%1,%2,%3};" \
        : "+f"((d)[0]), "+f"((d)[1]), "+f"((d)[2]), "+f"((d)[3]) \
        : "r"((av).x), "r"((av).y), "r"((av).z), "r"((av).w), \
          "r"((bv).x), "r"((bv).y))

// ============================ main GEMM kernel ============================
// 256 threads = 8 warps as 2(M)x4(N); warp tile 64x32; per-warp 4x4 m16n8k16.
// Fragment layout (PTX m16n8k16.f16, row.col):
//   A uint4 at ((ks*8+mblk)*32+lane): a0=(m=g,k=2q,2q+1) a1=(g+8,..)
//                                     a2=(g,8+2q,..)     a3=(g+8,8+2q,..)
//   B uint2 at ((ks*16+nblk)*32+lane): b0=(k=2q,2q+1; n=g) b1=(k=8+2q,..; n=g)
//   C: c0=(g,2q) c1=(g,2q+1) c2=(g+8,2q) c3=(g+8,2q+1)
template <int MODE>
__global__ void __launch_bounds__(256, 2)
moe_gemm(const uint4* __restrict__ Ap,
         const uint2* __restrict__ Bp,
         const float* __restrict__ bias,
         float* __restrict__ outp)
{
    extern __shared__ __align__(1024) char smem_c[];
    __shared__ __align__(8) unsigned long long mb[2 * STAGES];   // full[0..2], empty[3..5]

    const int NT    = (MODE == 0) ? 32 : 16;
    const int tid   = threadIdx.x;
    const int mtile = blockIdx.x;
    const int ntile = blockIdx.y;
    const int e     = blockIdx.z;

    const int wid  = tid >> 5;                 // 0..7
    const int lane = tid & 31;
    const int g    = lane >> 2;                // 0..7
    const int q    = lane & 3;                 // 0..3
    const int wm   = wid & 1;                  // M half
    const int wn   = wid >> 1;                 // N quarter 0..3

    const uint4* Abase = Ap + (((size_t)e * 32 + mtile) * NCHUNK) * A_U4;
    const uint2* Bbase = Bp + (((size_t)e * NT + ntile) * NCHUNK) * B_U2;

    const uint32_t smem_u = smem_to_u32(smem_c);
    const uint32_t mb_u   = smem_to_u32(mb);
    #define FULL_MB(s)  (mb_u + (s) * 8u)
    #define EMPTY_MB(s) (mb_u + (STAGES + (s)) * 8u)

    if (tid == 0) {
        #pragma unroll
        for (int s = 0; s < STAGES; s++) {
            MBARRIER_INIT(FULL_MB(s), 1);
            MBARRIER_INIT(EMPTY_MB(s), NWARPS);
        }
        FENCE_PROXY_ASYNC();
    }
    __syncthreads();   // mbarrier init visible

    if (tid == 0) {
        #pragma unroll
        for (int p = 0; p < 2; p++) {
            MBARRIER_EXPECT_TX(FULL_MB(p), STG_BYTES);
            bulk_g2s(smem_u + p * STG_BYTES,           Abase + (size_t)p * A_U4, A_BYTES, FULL_MB(p));
            bulk_g2s(smem_u + p * STG_BYTES + A_BYTES, Bbase + (size_t)p * B_U2, B_BYTES, FULL_MB(p));
        }
    }

    float acc[4][4][4];
    #pragma unroll
    for (int mt = 0; mt < 4; mt++)
        #pragma unroll
        for (int nt = 0; nt < 4; nt++)
            #pragma unroll
            for (int r = 0; r < 4; r++) acc[mt][nt][r] = 0.0f;

    int s = 0;
    for (int c = 0; c < NCHUNK; c++) {
        if (tid == 0) {
            const int cn = c + 2;
            if (cn < NCHUNK) {
                const int spp = cn % 3;
                if (c >= 1) {
                    const int k = cn / 3;
                    MBARRIER_WAIT_PARITY_RELAXED(EMPTY_MB(spp), (k + 1) & 1);
                }
                MBARRIER_EXPECT_TX(FULL_MB(spp), STG_BYTES);
                bulk_g2s(smem_u + spp * STG_BYTES,           Abase + (size_t)cn * A_U4, A_BYTES, FULL_MB(spp));
                bulk_g2s(smem_u + spp * STG_BYTES + A_BYTES, Bbase + (size_t)cn * B_U2, B_BYTES, FULL_MB(spp));
            }
        }

        MBARRIER_WAIT_PARITY(FULL_MB(s), (c / 3) & 1);

        const uint4* fA = reinterpret_cast<const uint4*>(smem_c + s * STG_BYTES)
                        + wm * 128 + lane;                 // + ks*256 + mt*32
        const uint2* fB = reinterpret_cast<const uint2*>(smem_c + s * STG_BYTES + A_BYTES)
                        + wn * 128 + lane;                 // + ks*512 + nt*32

        #pragma unroll
        for (int ks = 0; ks < 4; ks++) {
            uint4 a4[4];
            #pragma unroll
            for (int mt = 0; mt < 4; mt++) a4[mt] = fA[ks * 256 + mt * 32];
            uint2 b2[4];
            #pragma unroll
            for (int nt = 0; nt < 4; nt++) b2[nt] = fB[ks * 512 + nt * 32];
            #pragma unroll
            for (int mt = 0; mt < 4; mt++)
                #pragma unroll
                for (int nt = 0; nt < 4; nt++)
                    MMA_F16(acc[mt][nt], a4[mt], b2[nt]);
        }

        __syncwarp();
        if (lane == 0) MBARRIER_ARRIVE(EMPTY_MB(s));

        s = (s == STAGES - 1) ? 0 : s + 1;
    }

    if (MODE == 0) {
        // ---- epilogue: bias + silu*up -> stage f32 act tile in smem,
        //      then repack to fp16 fragment order (GEMM2 A-block (mtile, ntile)).
        __syncthreads();                       // all warps done with pipeline smem
        float* act_s = reinterpret_cast<float*>(smem_c);   // [128][65]
        #pragma unroll
        for (int nt = 0; nt < 4; nt++) {
            const int f0 = ntile * BN + wn * 32 + nt * 8 + 2 * q;   // gate col (even)
            const float2 bgu = *reinterpret_cast<const float2*>(
                bias + (size_t)e * F2I + f0);
            const int ic = wn * 16 + nt * 4 + q;                    // local icol 0..63
            #pragma unroll
            for (int mt = 0; mt < 4; mt++) {
                const int r0 = wm * 64 + mt * 16 + g;
                float gg0 = acc[mt][nt][0] + bgu.x;
                float uu0 = acc[mt][nt][1] + bgu.y;
                float gg1 = acc[mt][nt][2] + bgu.x;
                float uu1 = acc[mt][nt][3] + bgu.y;
                act_s[r0 * 65 + ic]       = (gg0 * uu0) / (1.0f + __expf(-gg0));
                act_s[(r0 + 8) * 65 + ic] = (gg1 * uu1) / (1.0f + __expf(-gg1));
            }
        }
        __syncthreads();
        uint4* dst = g_actp + (((size_t)e * 32 + mtile) * NCHUNK + ntile) * A_U4;
        #pragma unroll
        for (int r = 0; r < 4; r++) {
            const int j    = tid + r * 256;            // 0..1023
            const int ln   = j & 31;
            const int mblk = (j >> 5) & 7;
            const int ks   = j >> 8;
            const int gg   = ln >> 2, qq = ln & 3;
            const int m0 = mblk * 16 + gg;
            const int k0 = ks * 16 + 2 * qq;
            uint4 o;
            o.x = f2h2(act_s[m0 * 65 + k0],           act_s[m0 * 65 + k0 + 1]);
            o.y = f2h2(act_s[(m0 + 8) * 65 + k0],     act_s[(m0 + 8) * 65 + k0 + 1]);
            o.z = f2h2(act_s[m0 * 65 + k0 + 8],       act_s[m0 * 65 + k0 + 9]);
            o.w = f2h2(act_s[(m0 + 8) * 65 + k0 + 8], act_s[(m0 + 8) * 65 + k0 + 9]);
            dst[j] = o;
        }
    } else {
        #pragma unroll
        for (int nt = 0; nt < 4; nt++) {
            const int h = ntile * BN + wn * 32 + nt * 8 + 2 * q;
            const float2 bb = *reinterpret_cast<const float2*>(
                bias + (size_t)e * HDIM + h);
            #pragma unroll
            for (int mt = 0; mt < 4; mt++) {
                const int m = mtile * BM + wm * 64 + mt * 16 + g;
                float* o0 = outp + ((size_t)e * ROWS + m) * HDIM + h;
                *reinterpret_cast<float2*>(o0) =
                    make_float2(acc[mt][nt][0] + bb.x, acc[mt][nt][1] + bb.y);
                *reinterpret_cast<float2*>(o0 + 8 * (size_t)HDIM) =
                    make_float2(acc[mt][nt][2] + bb.x, acc[mt][nt][3] + bb.y);
            }
        }
    }
}

// ============================ prep kernels ============================

// x [b][e][m][h] -> g_xp fragment-order fp16; one uint4 per thread.
__global__ void pack_x(const float* __restrict__ in) {
    const uint32_t i = blockIdx.x * 256 + threadIdx.x;   // 2^23 total
    const int ln    = i & 31;
    const int mblk  = (i >> 5) & 7;
    const int ks    = (i >> 8) & 3;
    const int c     = (i >> 10) & 31;
    const int mtile = (i >> 15) & 31;
    const int e     = i >> 20;
    const int g = ln >> 2, q = ln & 3;
    const int m0 = mtile * 128 + mblk * 16 + g;          // m0 and m0+8 share b
    const int k0 = c * 64 + ks * 16 + 2 * q;
    const int b = m0 >> 9, mm = m0 & 511;
    const float* row0 = in + (((size_t)(b * E_EXPERTS + e) << 9) + mm) * HDIM + k0;
    const float* row1 = row0 + 8 * (size_t)HDIM;
    uint4 o;
    o.x = f2h2(row0[0], row0[1]);
    o.y = f2h2(row1[0], row1[1]);
    o.z = f2h2(row0[8], row0[9]);
    o.w = f2h2(row1[8], row1[9]);
    g_xp[i] = o;
}

// weights [e][2048][NB] -> fragment-order fp16 B; one uint2 per thread.
__global__ void pack_w(const float* __restrict__ in, uint2* __restrict__ outp,
                       int NT, int NB) {
    const uint32_t i = blockIdx.x * 256 + threadIdx.x;
    const int ln   = i & 31;
    const int nblk = (i >> 5) & 15;
    const int ks   = (i >> 9) & 3;
    const int c    = (i >> 11) & 31;
    const uint32_t r = i >> 16;
    const int ntile = (int)(r % (uint32_t)NT);
    const int e     = (int)(r / (uint32_t)NT);
    const int g = ln >> 2, q = ln & 3;
    const int n0 = ntile * 128 + nblk * 8 + g;
    const int k0 = c * 64 + ks * 16 + 2 * q;
    const float* src = in + ((size_t)e * 2048 + k0) * NB + n0;
    uint2 o;
    o.x = f2h2(src[0],             src[(size_t)NB]);        // k0, k0+1
    o.y = f2h2(src[(size_t)8 * NB], src[(size_t)9 * NB]);   // k0+8, k0+9
    outp[i] = o;
}

// ============================ host side ============================

extern "C" void kernel_launch(void* const* d_in, const int* in_sizes, int n_in,
                              void* d_out, int out_size)
{
    const float* dispatched = (const float*)d_in[0];   // (1,8,8,512,2048)
    const float* w1         = (const float*)d_in[1];   // (8,2048,4096)
    const float* w1_bias    = (const float*)d_in[2];   // (8,4096)
    const float* w2         = (const float*)d_in[3];   // (8,2048,2048)
    const float* w2_bias    = (const float*)d_in[4];   // (8,2048)
    float* out = (float*)d_out;                        // (8,1,4096,2048) fp32
    (void)in_sizes; (void)n_in; (void)out_size;

    static uint4 *p_xp = nullptr, *p_actp = nullptr;
    static uint2 *p_w1p = nullptr, *p_w2p = nullptr;
    static cudaStream_t s2 = nullptr;
    static cudaEvent_t ev_fork = nullptr, ev_join = nullptr;
    static bool init_done = false;
    if (!init_done) {
        cudaGetSymbolAddress((void**)&p_xp,   g_xp);
        cudaGetSymbolAddress((void**)&p_actp, g_actp);
        cudaGetSymbolAddress((void**)&p_w1p,  g_w1p);
        cudaGetSymbolAddress((void**)&p_w2p,  g_w2p);
        cudaFuncSetAttribute(moe_gemm<0>, cudaFuncAttributeMaxDynamicSharedMemorySize, DYN_SMEM);
        cudaFuncSetAttribute(moe_gemm<1>, cudaFuncAttributeMaxDynamicSharedMemorySize, DYN_SMEM);
        cudaStreamCreateWithFlags(&s2, cudaStreamNonBlocking);
        cudaEventCreateWithFlags(&ev_fork, cudaEventDisableTiming);
        cudaEventCreateWithFlags(&ev_join, cudaEventDisableTiming);
        init_done = true;
    }

    // prep on stream 0: DRAM-bound, must precede GEMM1
    pack_x<<<32768, 256>>>(dispatched);
    pack_w<<<65536, 256>>>(w1, p_w1p, 32, F2I);

    // fork AFTER the DRAM-bound prep: pack_w2 now overlaps tensor-bound GEMM1
    // (which uses <5% DRAM) instead of contending with pack_x/pack_w1 for HBM.
    cudaEventRecord(ev_fork, 0);
    cudaStreamWaitEvent(s2, ev_fork, 0);
    pack_w<<<32768, 256, 0, s2>>>(w2, p_w2p, 16, HDIM);
    cudaEventRecord(ev_join, s2);

    // GEMM1: grid (32 mtiles, 32 ntiles, 8 experts), 256 threads
    moe_gemm<0><<<dim3(32, 32, E_EXPERTS), 256, DYN_SMEM>>>(p_xp, p_w1p, w1_bias, nullptr);

    // join: GEMM2 needs g_w2p
    cudaStreamWaitEvent(0, ev_join, 0);
    // GEMM2: grid (32, 16, 8)
    moe_gemm<1><<<dim3(32, 16, E_EXPERTS), 256, DYN_SMEM>>>(p_actp, p_w2p, w2_bias, out);
}

// round 17
// speedup vs baseline: 1.0358x; 1.0050x over previous
#include <cuda_runtime.h>
#include <cuda_fp16.h>
#include <math.h>
#include <stdint.h>

// ============================================================================
// FusedExpertsWrapper — FP16 mma.sync(m16n8k16) + cp.async.bulk, warp-
// autonomous pipeline, fragment-order packed operands (R14 = R13 GEMM kernels,
// per-expert launch pipelining across 3 streams).
//   GEMM1: gu = x@w1 + b1 ; act = silu(gu_even)*gu_odd
//   GEMM2: out = act@w2 + b2
// Per-expert chains: prep(e) -> G1(e) -> G2(e), with G2(e-1) co-running with
// G1(e) (tensor-bound kernels backfill each other's wave tails) and all prep
// except the first expert's hidden under GEMM work.
// fp32 accumulate; rel_err ~5e-4 (threshold 1e-3).
// ============================================================================

#define E_EXPERTS 8
#define HDIM      2048
#define IDIM      2048
#define F2I       4096
#define ROWS      4096

// ---------------- tiling ----------------
#define BM      128
#define BN      128
#define BK      64
#define STAGES  3
#define A_BYTES    16384                     // 128 x 64 fp16
#define B_BYTES    16384                     // 64 x 128 fp16
#define STG_BYTES  (A_BYTES + B_BYTES)       // 32768
#define DYN_SMEM   (STAGES * STG_BYTES)      // 98304 -> 2 CTAs/SM
#define NCHUNK  (HDIM / BK)                  // 32
#define NWARPS  8
#define A_U4    1024                         // uint4 per A block
#define B_U2    2048                         // uint2 per B block

// ---------------- packed scratch (fragment-order fp16) ----------------
// A blocks: [e][mtile 32][chunk 32][1024 uint4]  (2^20 uint4 per expert)
__device__ uint4 g_xp  [(size_t)E_EXPERTS * 32 * NCHUNK * A_U4];
__device__ uint4 g_actp[(size_t)E_EXPERTS * 32 * NCHUNK * A_U4];
// B blocks: [e][ntile NT][chunk 32][2048 uint2]  (NT*2^16 uint2 per expert)
__device__ uint2 g_w1p [(size_t)E_EXPERTS * 32 * NCHUNK * B_U2];
__device__ uint2 g_w2p [(size_t)E_EXPERTS * 16 * NCHUNK * B_U2];

__device__ __forceinline__ uint32_t f2h2(float lo, float hi) {
    __half2 h = __floats2half2_rn(lo, hi);
    return *reinterpret_cast<uint32_t*>(&h);
}
__device__ __forceinline__ uint32_t smem_to_u32(const void* p) {
    uint32_t a;
    asm("{ .reg .u64 t; cvta.to.shared.u64 t, %1; cvt.u32.u64 %0, t; }" : "=r"(a) : "l"(p));
    return a;
}

#define MBARRIER_INIT(addr, cnt) \
    asm volatile("mbarrier.init.shared.b64 [%0], %1;" :: "r"((uint32_t)(addr)), "r"((uint32_t)(cnt)) : "memory")
#define MBARRIER_EXPECT_TX(addr, bytes) \
    asm volatile("mbarrier.arrive.expect_tx.shared.b64 _, [%0], %1;" :: "r"((uint32_t)(addr)), "r"((uint32_t)(bytes)) : "memory")
#define MBARRIER_ARRIVE(addr) \
    asm volatile("mbarrier.arrive.shared.b64 _, [%0];" :: "r"((uint32_t)(addr)) : "memory")
#define FENCE_PROXY_ASYNC() asm volatile("fence.proxy.async.shared::cta;" ::: "memory")

#define MBARRIER_WAIT_PARITY(mbar_smem_addr, phase_parity) do { \
    uint32_t _mbar = (uint32_t)(mbar_smem_addr); \
    uint32_t _parity = (uint32_t)(phase_parity); \
    uint32_t _done; \
    asm volatile( \
        "{\n\t.reg .pred p;\n\t" \
        "mbarrier.try_wait.parity.acquire.cta.shared::cta.b64 p, [%1], %2;\n\t" \
        "selp.b32 %0, 1, 0, p;\n\t}" \
        : "=r"(_done) : "r"(_mbar), "r"(_parity) : "memory"); \
    if (!_done) { \
        asm volatile( \
            "{\n\t.reg .pred P1;\n\t" \
            "WAIT_LOOP_%=:\n\t" \
            "mbarrier.try_wait.parity.acquire.cta.shared::cta.b64 P1, [%0], %1, 0x989680;\n\t" \
            "@P1 bra.uni WAIT_DONE_%=;\n\t" \
            "bra.uni WAIT_LOOP_%=;\n\t" \
            "WAIT_DONE_%=:\n\t}" \
            :: "r"(_mbar), "r"(_parity) : "memory"); \
    } \
} while (0)

#define MBARRIER_WAIT_PARITY_RELAXED(mbar_smem_addr, phase_parity) do { \
    uint32_t _mbar = (uint32_t)(mbar_smem_addr); \
    uint32_t _parity = (uint32_t)(phase_parity); \
    uint32_t _done; \
    asm volatile( \
        "{\n\t.reg .pred p;\n\t" \
        "mbarrier.try_wait.parity.relaxed.cta.shared::cta.b64 p, [%1], %2, 0x989680;\n\t" \
        "selp.b32 %0, 1, 0, p;\n\t}" \
        : "=r"(_done) : "r"(_mbar), "r"(_parity) : "memory"); \
    if (!_done) { \
        asm volatile( \
            "{\n\t.reg .pred P1;\n\t" \
            "WAIT_LOOP_%=:\n\t" \
            "mbarrier.try_wait.parity.relaxed.cta.shared::cta.b64 P1, [%0], %1, 0x989680;\n\t" \
            "@P1 bra.uni WAIT_DONE_%=;\n\t" \
            "bra.uni WAIT_LOOP_%=;\n\t" \
            "WAIT_DONE_%=:\n\t}" \
            :: "r"(_mbar), "r"(_parity) : "memory"); \
    } \
} while (0)

__device__ __forceinline__ void bulk_g2s(uint32_t sdst, const void* gsrc,
                                         uint32_t bytes, uint32_t mbar) {
    asm volatile(
        "cp.async.bulk.shared::cluster.global.mbarrier::complete_tx::bytes "
        "[%0], [%1], %2, [%3];"
        :: "r"(sdst), "l"(gsrc), "r"(bytes), "r"(mbar) : "memory");
}

#define MMA_F16(d, av, bv) \
    asm volatile("mma.sync.aligned.m16n8k16.row.col.f32.f16.f16.f32 " \
        "{%0,%1,%2,%3}, {%4,%5,%6,%7}, {%8,%9}, {%0,%1,%2,%3};" \
        : "+f"((d)[0]), "+f"((d)[1]), "+f"((d)[2]), "+f"((d)[3]) \
        : "r"((av).x), "r"((av).y), "r"((av).z), "r"((av).w), \
          "r"((bv).x), "r"((bv).y))

// ============================ main GEMM kernel ============================
// 256 threads = 8 warps as 2(M)x4(N); warp tile 64x32; per-warp 4x4 m16n8k16.
// Per-expert launch: grid (32 mtiles, NT ntiles), expert index passed as arg.
template <int MODE>
__global__ void __launch_bounds__(256, 2)
moe_gemm(const uint4* __restrict__ Ap,
         const uint2* __restrict__ Bp,
         const float* __restrict__ bias,
         float* __restrict__ outp,
         int e)
{
    extern __shared__ __align__(1024) char smem_c[];
    __shared__ __align__(8) unsigned long long mb[2 * STAGES];   // full[0..2], empty[3..5]

    const int NT    = (MODE == 0) ? 32 : 16;
    const int tid   = threadIdx.x;
    const int mtile = blockIdx.x;
    const int ntile = blockIdx.y;

    const int wid  = tid >> 5;                 // 0..7
    const int lane = tid & 31;
    const int g    = lane >> 2;                // 0..7
    const int q    = lane & 3;                 // 0..3
    const int wm   = wid & 1;                  // M half
    const int wn   = wid >> 1;                 // N quarter 0..3

    const uint4* Abase = Ap + (((size_t)e * 32 + mtile) * NCHUNK) * A_U4;
    const uint2* Bbase = Bp + (((size_t)e * NT + ntile) * NCHUNK) * B_U2;

    const uint32_t smem_u = smem_to_u32(smem_c);
    const uint32_t mb_u   = smem_to_u32(mb);
    #define FULL_MB(s)  (mb_u + (s) * 8u)
    #define EMPTY_MB(s) (mb_u + (STAGES + (s)) * 8u)

    if (tid == 0) {
        #pragma unroll
        for (int s = 0; s < STAGES; s++) {
            MBARRIER_INIT(FULL_MB(s), 1);
            MBARRIER_INIT(EMPTY_MB(s), NWARPS);
        }
        FENCE_PROXY_ASYNC();
    }
    __syncthreads();   // mbarrier init visible

    if (tid == 0) {
        #pragma unroll
        for (int p = 0; p < 2; p++) {
            MBARRIER_EXPECT_TX(FULL_MB(p), STG_BYTES);
            bulk_g2s(smem_u + p * STG_BYTES,           Abase + (size_t)p * A_U4, A_BYTES, FULL_MB(p));
            bulk_g2s(smem_u + p * STG_BYTES + A_BYTES, Bbase + (size_t)p * B_U2, B_BYTES, FULL_MB(p));
        }
    }

    float acc[4][4][4];
    #pragma unroll
    for (int mt = 0; mt < 4; mt++)
        #pragma unroll
        for (int nt = 0; nt < 4; nt++)
            #pragma unroll
            for (int r = 0; r < 4; r++) acc[mt][nt][r] = 0.0f;

    int s = 0;
    for (int c = 0; c < NCHUNK; c++) {
        if (tid == 0) {
            const int cn = c + 2;
            if (cn < NCHUNK) {
                const int spp = cn % 3;
                if (c >= 1) {
                    const int k = cn / 3;
                    MBARRIER_WAIT_PARITY_RELAXED(EMPTY_MB(spp), (k + 1) & 1);
                }
                MBARRIER_EXPECT_TX(FULL_MB(spp), STG_BYTES);
                bulk_g2s(smem_u + spp * STG_BYTES,           Abase + (size_t)cn * A_U4, A_BYTES, FULL_MB(spp));
                bulk_g2s(smem_u + spp * STG_BYTES + A_BYTES, Bbase + (size_t)cn * B_U2, B_BYTES, FULL_MB(spp));
            }
        }

        MBARRIER_WAIT_PARITY(FULL_MB(s), (c / 3) & 1);

        const uint4* fA = reinterpret_cast<const uint4*>(smem_c + s * STG_BYTES)
                        + wm * 128 + lane;                 // + ks*256 + mt*32
        const uint2* fB = reinterpret_cast<const uint2*>(smem_c + s * STG_BYTES + A_BYTES)
                        + wn * 128 + lane;                 // + ks*512 + nt*32

        #pragma unroll
        for (int ks = 0; ks < 4; ks++) {
            uint4 a4[4];
            #pragma unroll
            for (int mt = 0; mt < 4; mt++) a4[mt] = fA[ks * 256 + mt * 32];
            uint2 b2[4];
            #pragma unroll
            for (int nt = 0; nt < 4; nt++) b2[nt] = fB[ks * 512 + nt * 32];
            #pragma unroll
            for (int mt = 0; mt < 4; mt++)
                #pragma unroll
                for (int nt = 0; nt < 4; nt++)
                    MMA_F16(acc[mt][nt], a4[mt], b2[nt]);
        }

        __syncwarp();
        if (lane == 0) MBARRIER_ARRIVE(EMPTY_MB(s));

        s = (s == STAGES - 1) ? 0 : s + 1;
    }

    if (MODE == 0) {
        // ---- epilogue: bias + silu*up -> stage f32 act tile in smem,
        //      then repack to fp16 fragment order (GEMM2 A-block (mtile, ntile)).
        __syncthreads();                       // all warps done with pipeline smem
        float* act_s = reinterpret_cast<float*>(smem_c);   // [128][65]
        #pragma unroll
        for (int nt = 0; nt < 4; nt++) {
            const int f0 = ntile * BN + wn * 32 + nt * 8 + 2 * q;   // gate col (even)
            const float2 bgu = *reinterpret_cast<const float2*>(
                bias + (size_t)e * F2I + f0);
            const int ic = wn * 16 + nt * 4 + q;                    // local icol 0..63
            #pragma unroll
            for (int mt = 0; mt < 4; mt++) {
                const int r0 = wm * 64 + mt * 16 + g;
                float gg0 = acc[mt][nt][0] + bgu.x;
                float uu0 = acc[mt][nt][1] + bgu.y;
                float gg1 = acc[mt][nt][2] + bgu.x;
                float uu1 = acc[mt][nt][3] + bgu.y;
                act_s[r0 * 65 + ic]       = (gg0 * uu0) / (1.0f + __expf(-gg0));
                act_s[(r0 + 8) * 65 + ic] = (gg1 * uu1) / (1.0f + __expf(-gg1));
            }
        }
        __syncthreads();
        uint4* dst = g_actp + (((size_t)e * 32 + mtile) * NCHUNK + ntile) * A_U4;
        #pragma unroll
        for (int r = 0; r < 4; r++) {
            const int j    = tid + r * 256;            // 0..1023
            const int ln   = j & 31;
            const int mblk = (j >> 5) & 7;
            const int ks   = j >> 8;
            const int gg   = ln >> 2, qq = ln & 3;
            const int m0 = mblk * 16 + gg;
            const int k0 = ks * 16 + 2 * qq;
            uint4 o;
            o.x = f2h2(act_s[m0 * 65 + k0],           act_s[m0 * 65 + k0 + 1]);
            o.y = f2h2(act_s[(m0 + 8) * 65 + k0],     act_s[(m0 + 8) * 65 + k0 + 1]);
            o.z = f2h2(act_s[m0 * 65 + k0 + 8],       act_s[m0 * 65 + k0 + 9]);
            o.w = f2h2(act_s[(m0 + 8) * 65 + k0 + 8], act_s[(m0 + 8) * 65 + k0 + 9]);
            dst[j] = o;
        }
    } else {
        #pragma unroll
        for (int nt = 0; nt < 4; nt++) {
            const int h = ntile * BN + wn * 32 + nt * 8 + 2 * q;
            const float2 bb = *reinterpret_cast<const float2*>(
                bias + (size_t)e * HDIM + h);
            #pragma unroll
            for (int mt = 0; mt < 4; mt++) {
                const int m = mtile * BM + wm * 64 + mt * 16 + g;
                float* o0 = outp + ((size_t)e * ROWS + m) * HDIM + h;
                *reinterpret_cast<float2*>(o0) =
                    make_float2(acc[mt][nt][0] + bb.x, acc[mt][nt][1] + bb.y);
                *reinterpret_cast<float2*>(o0 + 8 * (size_t)HDIM) =
                    make_float2(acc[mt][nt][2] + bb.x, acc[mt][nt][3] + bb.y);
            }
        }
    }
}

// ============================ prep kernels (per expert) ============================

// x [b][e][m][h] -> g_xp fragment-order fp16; one uint4 per thread; 2^20/expert.
__global__ void pack_x(const float* __restrict__ in, int e) {
    const uint32_t i = blockIdx.x * 256 + threadIdx.x;   // < 2^20
    const int ln    = i & 31;
    const int mblk  = (i >> 5) & 7;
    const int ks    = (i >> 8) & 3;
    const int c     = (i >> 10) & 31;
    const int mtile = (i >> 15) & 31;
    const int g = ln >> 2, q = ln & 3;
    const int m0 = mtile * 128 + mblk * 16 + g;          // m0 and m0+8 share b
    const int k0 = c * 64 + ks * 16 + 2 * q;
    const int b = m0 >> 9, mm = m0 & 511;
    const float* row0 = in + (((size_t)(b * E_EXPERTS + e) << 9) + mm) * HDIM + k0;
    const float* row1 = row0 + 8 * (size_t)HDIM;
    uint4 o;
    o.x = f2h2(row0[0], row0[1]);
    o.y = f2h2(row1[0], row1[1]);
    o.z = f2h2(row0[8], row0[9]);
    o.w = f2h2(row1[8], row1[9]);
    g_xp[((size_t)e << 20) + i] = o;
}

// one expert's weights [2048][NB] -> fragment-order fp16 B; NT*2^16 uint2.
__global__ void pack_w(const float* __restrict__ in, uint2* __restrict__ outp,
                       int NT, int NB) {
    const uint32_t i = blockIdx.x * 256 + threadIdx.x;   // < NT<<16
    const int ln   = i & 31;
    const int nblk = (i >> 5) & 15;
    const int ks   = (i >> 9) & 3;
    const int c    = (i >> 11) & 31;
    const int ntile = (int)(i >> 16);
    const int g = ln >> 2, q = ln & 3;
    const int n0 = ntile * 128 + nblk * 8 + g;
    const int k0 = c * 64 + ks * 16 + 2 * q;
    const float* src = in + (size_t)k0 * NB + n0;
    uint2 o;
    o.x = f2h2(src[0],              src[(size_t)NB]);       // k0, k0+1
    o.y = f2h2(src[(size_t)8 * NB], src[(size_t)9 * NB]);   // k0+8, k0+9
    outp[i] = o;
}

// ============================ host side ============================

extern "C" void kernel_launch(void* const* d_in, const int* in_sizes, int n_in,
                              void* d_out, int out_size)
{
    const float* dispatched = (const float*)d_in[0];   // (1,8,8,512,2048)
    const float* w1         = (const float*)d_in[1];   // (8,2048,4096)
    const float* w1_bias    = (const float*)d_in[2];   // (8,4096)
    const float* w2         = (const float*)d_in[3];   // (8,2048,2048)
    const float* w2_bias    = (const float*)d_in[4];   // (8,2048)
    float* out = (float*)d_out;                        // (8,1,4096,2048) fp32
    (void)in_sizes; (void)n_in; (void)out_size;

    static uint4 *p_xp = nullptr, *p_actp = nullptr;
    static uint2 *p_w1p = nullptr, *p_w2p = nullptr;
    static cudaStream_t s_prep = nullptr, s_g2 = nullptr;
    static cudaEvent_t ev_fork = nullptr, ev_join = nullptr;
    static cudaEvent_t ev1[E_EXPERTS], ev2[E_EXPERTS], evg1[E_EXPERTS];
    static bool init_done = false;
    if (!init_done) {
        cudaGetSymbolAddress((void**)&p_xp,   g_xp);
        cudaGetSymbolAddress((void**)&p_actp, g_actp);
        cudaGetSymbolAddress((void**)&p_w1p,  g_w1p);
        cudaGetSymbolAddress((void**)&p_w2p,  g_w2p);
        cudaFuncSetAttribute(moe_gemm<0>, cudaFuncAttributeMaxDynamicSharedMemorySize, DYN_SMEM);
        cudaFuncSetAttribute(moe_gemm<1>, cudaFuncAttributeMaxDynamicSharedMemorySize, DYN_SMEM);
        cudaStreamCreateWithFlags(&s_prep, cudaStreamNonBlocking);
        cudaStreamCreateWithFlags(&s_g2,   cudaStreamNonBlocking);
        cudaEventCreateWithFlags(&ev_fork, cudaEventDisableTiming);
        cudaEventCreateWithFlags(&ev_join, cudaEventDisableTiming);
        for (int e = 0; e < E_EXPERTS; e++) {
            cudaEventCreateWithFlags(&ev1[e],  cudaEventDisableTiming);
            cudaEventCreateWithFlags(&ev2[e],  cudaEventDisableTiming);
            cudaEventCreateWithFlags(&evg1[e], cudaEventDisableTiming);
        }
        init_done = true;
    }

    // fork the prep stream into the capture
    cudaEventRecord(ev_fork, 0);
    cudaStreamWaitEvent(s_prep, ev_fork, 0);

    // s_prep: per-expert prep chains. pack_x+pack_w1 -> ev1[e]; pack_w2 -> ev2[e].
    for (int e = 0; e < E_EXPERTS; e++) {
        pack_x<<<4096, 256, 0, s_prep>>>(dispatched, e);
        pack_w<<<32 * 256, 256, 0, s_prep>>>(w1 + (size_t)e * HDIM * F2I,
                                             p_w1p + ((size_t)e * 32 << 16), 32, F2I);
        cudaEventRecord(ev1[e], s_prep);
        pack_w<<<16 * 256, 256, 0, s_prep>>>(w2 + (size_t)e * IDIM * HDIM,
                                             p_w2p + ((size_t)e * 16 << 16), 16, HDIM);
        cudaEventRecord(ev2[e], s_prep);
    }

    // s0: GEMM1 per expert (each waits its prep)
    for (int e = 0; e < E_EXPERTS; e++) {
        cudaStreamWaitEvent(0, ev1[e], 0);
        moe_gemm<0><<<dim3(32, 32), 256, DYN_SMEM>>>(p_xp, p_w1p, w1_bias, nullptr, e);
        cudaEventRecord(evg1[e], 0);
    }

    // s_g2: GEMM2 per expert (waits GEMM1(e) + pack_w2(e)); co-runs with GEMM1(e+1..)
    for (int e = 0; e < E_EXPERTS; e++) {
        cudaStreamWaitEvent(s_g2, evg1[e], 0);
        cudaStreamWaitEvent(s_g2, ev2[e], 0);
        moe_gemm<1><<<dim3(32, 16), 256, DYN_SMEM, s_g2>>>(p_actp, p_w2p, w2_bias, out, e);
    }

    // join everything back to stream 0
    cudaEventRecord(ev_join, s_g2);
    cudaStreamWaitEvent(0, ev_join, 0);
}